// round 17
// baseline (speedup 1.0000x reference)
#include <cuda_runtime.h>
#include <cstdint>

#define T_STEPS 50
#define NB2 32          // fallback scan CTAs
#define CL 16           // cluster CTAs; each owns 16 of 256 hidden units

// ---------------- scratch (device globals; no allocation) ----------------
__device__ float    g_pre[T_STEPS * 768];   // Wih_low[:, :256]@x_t + bih_low
__device__ float    g_xc [T_STEPS * 256];   // concat(f_v, f_m)
__device__ float    g_Lout[T_STEPS * 256];  // h1 per step
__device__ float    g_h1[2][256];           // fallback state
__device__ float    g_h2[2][256];
__device__ unsigned g_slots[NB2];           // fallback barrier slots

// ---------------- helpers ----------------
__device__ __forceinline__ float warpsum(float v) {
    v += __shfl_xor_sync(0xffffffffu, v, 16);
    v += __shfl_xor_sync(0xffffffffu, v, 8);
    v += __shfl_xor_sync(0xffffffffu, v, 4);
    v += __shfl_xor_sync(0xffffffffu, v, 2);
    v += __shfl_xor_sync(0xffffffffu, v, 1);
    return v;
}
__device__ __forceinline__ float eluf(float x) { return x > 0.f ? x : expm1f(x); }
__device__ __forceinline__ float sigf(float x) { return 1.f / (1.f + expf(-x)); }
// fast variants for scan gates only (err ~1e-6; tolerance 1e-3)
__device__ __forceinline__ float sigF(float x) {
    return __fdividef(1.f, 1.f + __expf(-x));
}
__device__ __forceinline__ float tanF(float x) {
    return 2.f * __fdividef(1.f, 1.f + __expf(-2.f * x)) - 1.f;
}
__device__ __forceinline__ float dot4(float4 a, float4 b) {
    return a.x * b.x + a.y * b.y + a.z * b.z + a.w * b.w;
}
__device__ __forceinline__ uint32_t s2u(const void* p) {
    uint32_t a;
    asm("{ .reg .u64 t; cvta.to.shared.u64 t, %1; cvt.u32.u64 %0, t; }"
        : "=r"(a) : "l"(p));
    return a;
}
__device__ __forceinline__ uint32_t mapa_rk(uint32_t laddr, int rk) {
    uint32_t ra;
    asm volatile("mapa.shared::cluster.u32 %0, %1, %2;"
                 : "=r"(ra) : "r"(laddr), "r"(rk));
    return ra;
}
__device__ __forceinline__ void dsm_store2(uint32_t ra, uint32_t vb, uint32_t ep) {
    asm volatile("st.shared::cluster.v2.u32 [%0], {%1, %2};"
                 :: "r"(ra), "r"(vb), "r"(ep) : "memory");
}
__device__ __forceinline__ float poll_mb(uint32_t addr, uint32_t want) {
    uint32_t v, e;
    do {
        asm volatile("ld.volatile.shared.v2.u32 {%0, %1}, [%2];"
                     : "=r"(v), "=r"(e) : "r"(addr));
    } while (e != want);
    return __uint_as_float(v);
}
#define CLUSTER_ARRIVE() asm volatile("barrier.cluster.arrive.aligned;" ::: "memory")
#define CLUSTER_WAIT()   asm volatile("barrier.cluster.wait.aligned;"   ::: "memory")

// fallback epoch barrier (proven)
__device__ __forceinline__ void gridbar(unsigned epoch, int tid, int cta) {
    __syncthreads();
    if (tid == 0)
        asm volatile("st.release.gpu.global.u32 [%0], %1;"
                     :: "l"(g_slots + cta), "r"(epoch) : "memory");
    if (tid < 32) {
        unsigned v;
        do {
            asm volatile("ld.acquire.gpu.global.u32 %0, [%1];"
                         : "=r"(v) : "l"(g_slots + tid) : "memory");
        } while (__any_sync(0xffffffffu, v < epoch));
    }
    __syncthreads();
}

// ---------------- k1a: f_v / f_m -> g_xc (grid 50x8, 16 rows/block) ---------
__global__ void __launch_bounds__(256) k1a_feat(
    const float* __restrict__ v0, const float* __restrict__ m0,
    const float* __restrict__ W1v, const float* __restrict__ b1v,
    const float* __restrict__ W1m, const float* __restrict__ b1m)
{
    int t = blockIdx.x, q = blockIdx.y;
    int tid = threadIdx.x, warp = tid >> 5, lane = tid & 31;
    __shared__ __align__(16) float xv[768];
    for (int i = tid; i < 768; i += 256) xv[i] = v0[t * 768 + i];
    __syncthreads();

    const float4* xv4 = (const float4*)xv;
    float p[2];
#pragma unroll
    for (int u = 0; u < 2; u++) {
        int i = q * 16 + warp + 8 * u;
        const float4* w = (const float4*)(W1v + i * 768);
        float s = 0.f;
#pragma unroll
        for (int k = 0; k < 6; k++)
            s += dot4(__ldg(w + lane + 32 * k), xv4[lane + 32 * k]);
        p[u] = s;
    }
#pragma unroll
    for (int u = 0; u < 2; u++) {
        p[u] = warpsum(p[u]);
        int i = q * 16 + warp + 8 * u;
        if (lane == 0) g_xc[t * 256 + i] = eluf(p[u] + b1v[i]);
    }
    if (q == 0 && tid < 128) {
        float ma = m0[t * 2 + 0], mb = m0[t * 2 + 1];
        g_xc[t * 256 + 128 + tid] =
            eluf(ma * W1m[tid * 2] + mb * W1m[tid * 2 + 1] + b1m[tid]);
    }
    if (t == 0 && q == 0) {
        if (tid < 256) {
            g_h1[0][tid] = 0.f; g_h1[1][tid] = 0.f;
            g_h2[0][tid] = 0.f; g_h2[1][tid] = 0.f;
        }
        if (tid < NB2) g_slots[tid] = 0u;
    }
}

// ---------------- k1b: pre = WihL[:, :256]@xc + bihL (grid 50x12, 64 rows) --
__global__ void __launch_bounds__(256) k1b_pre(
    const float* __restrict__ WihL, const float* __restrict__ bihL)
{
    int t = blockIdx.x, s = blockIdx.y;
    int tid = threadIdx.x, warp = tid >> 5, lane = tid & 31;
    __shared__ __align__(16) float xc[256];
    if (tid < 256) xc[tid] = g_xc[t * 256 + tid];
    __syncthreads();
    const float4* xc4 = (const float4*)xc;

#pragma unroll
    for (int b = 0; b < 2; b++) {
        float p[4];
#pragma unroll
        for (int u = 0; u < 4; u++) {
            int g = s * 64 + warp + 8 * (b * 4 + u);
            const float4* w = (const float4*)(WihL + g * 512);
            p[u] = dot4(__ldg(w + lane), xc4[lane]) +
                   dot4(__ldg(w + lane + 32), xc4[lane + 32]);
        }
#pragma unroll
        for (int u = 0; u < 4; u++) {
            p[u] = warpsum(p[u]);
            int g = s * 64 + warp + 8 * (b * 4 + u);
            if (lane == 0) g_pre[t * 768 + g] = p[u] + bihL[g];
        }
    }
}

// ======= k2 cluster v17: warp-per-unit, float4 register weights ==============
// Warp w of rank owns hidden unit j = rank*16 + w. Register rows (float4,
// r12-proven footprint: 24 float4 = 96 regs):
//   wA[r]   = WihL[j+256r, 256:512]  (x = h2_old)     r = 0..2
//   wA[3+r] = WhhL[j+256r]           (x = h1_old)
//   wB[r]   = WihH[j+256r]           (x = h1_new)
//   wB[3+r] = WhhH[j+256r]           (x = h2_old)
// After warpsum every lane holds all 6 sums -> gates in-warp, zero dots smem.
// Lanes 0..15 push the unit's h to rank==lane (pre-mapa'd, 1 store/lane).
// One __syncthreads per phase (after poll); all other hazards are fenced by
// the polls' own-push dependency (consumer of element j can't pass its poll
// until owner warp j pushed, which happens after the owner's old-value read).
__global__ void __launch_bounds__(512, 1) k2_cluster(
    const float* __restrict__ WihL, const float* __restrict__ WhhL,
    const float* __restrict__ bhhLg,
    const float* __restrict__ WihH, const float* __restrict__ WhhH,
    const float* __restrict__ bihHg, const float* __restrict__ bhhHg)
{
    __shared__ __align__(16) float h1c[256], h2c[256];
    __shared__ __align__(8) uint2 mb1[2][256], mb2[2][256];
    __shared__ float sbhhL[48], sbihH[48], sbhhH[48];

    int tid = threadIdx.x, warp = tid >> 5, lane = tid & 31;
    uint32_t rank;
    asm("mov.u32 %0, %%cluster_ctarank;" : "=r"(rank));
    int j0 = (int)rank * 16;
    int j = j0 + warp;                     // this warp's hidden unit

    float4 wA[6][2], wB[6][2];
#pragma unroll
    for (int r = 0; r < 3; r++) {
        int row = j + 256 * r;
        const float4* pa0 = (const float4*)(WihL + row * 512 + 256);
        const float4* pa1 = (const float4*)(WhhL + row * 256);
        const float4* pb0 = (const float4*)(WihH + row * 256);
        const float4* pb1 = (const float4*)(WhhH + row * 256);
        wA[r][0]     = __ldg(pa0 + lane * 2); wA[r][1]     = __ldg(pa0 + lane * 2 + 1);
        wA[3 + r][0] = __ldg(pa1 + lane * 2); wA[3 + r][1] = __ldg(pa1 + lane * 2 + 1);
        wB[r][0]     = __ldg(pb0 + lane * 2); wB[r][1]     = __ldg(pb0 + lane * 2 + 1);
        wB[3 + r][0] = __ldg(pb1 + lane * 2); wB[3 + r][1] = __ldg(pb1 + lane * 2 + 1);
    }
    if (tid < 48) {
        int jj = tid / 3, r = tid % 3, row = j0 + jj + 256 * r;
        sbhhL[tid] = __ldg(bhhLg + row);
        sbihH[tid] = __ldg(bihHg + row);
        sbhhH[tid] = __ldg(bhhHg + row);
    }
    if (tid < 256) {
        h1c[tid] = 0.f;  h2c[tid] = 0.f;
        mb1[0][tid] = make_uint2(0u, 0u);  mb1[1][tid] = make_uint2(0u, 0u);
        mb2[0][tid] = make_uint2(0u, 0u);  mb2[1][tid] = make_uint2(0u, 0u);
    }
    uint32_t pl1[2], pl2[2];               // local poll addrs (tid<256)
    if (tid < 256) {
#pragma unroll
        for (int b = 0; b < 2; b++) {
            pl1[b] = s2u(&mb1[b][tid]);
            pl2[b] = s2u(&mb2[b][tid]);
        }
    }
    uint32_t raM1[2], raM2[2];             // remote push addrs (lane<16)
    if (lane < 16) {
#pragma unroll
        for (int b = 0; b < 2; b++) {
            raM1[b] = mapa_rk(s2u(&mb1[b][j]), lane);
            raM2[b] = mapa_rk(s2u(&mb2[b][j]), lane);
        }
    }
    __syncthreads();
    CLUSTER_ARRIVE(); CLUSTER_WAIT();      // all inits visible before any push

    for (int t = 0; t < T_STEPS; t++) {
        int cb = t & 1, nb = cb ^ 1;

        // pre loads for this unit (warp-uniform -> broadcast; latency hidden)
        const float* pg = g_pre + t * 768 + j;
        float pr = __ldcg(pg), pz = __ldcg(pg + 256), pn = __ldcg(pg + 512);

        // ---- phase A ----
        float a[6];
        {   // local hh dots first (h1c stable since previous phase-B sync)
            const float4* xp = (const float4*)h1c;
            float4 xlo = xp[lane * 2], xhi = xp[lane * 2 + 1];
            a[3] = dot4(wA[3][0], xlo) + dot4(wA[3][1], xhi);
            a[4] = dot4(wA[4][0], xlo) + dot4(wA[4][1], xhi);
            a[5] = dot4(wA[5][0], xlo) + dot4(wA[5][1], xhi);
        }
        if (tid < 256)
            h2c[tid] = poll_mb(pl2[cb], (uint32_t)t);
        __syncthreads();
        {
            const float4* xp = (const float4*)h2c;
            float4 xlo = xp[lane * 2], xhi = xp[lane * 2 + 1];
            a[0] = dot4(wA[0][0], xlo) + dot4(wA[0][1], xhi);
            a[1] = dot4(wA[1][0], xlo) + dot4(wA[1][1], xhi);
            a[2] = dot4(wA[2][0], xlo) + dot4(wA[2][1], xhi);
        }
#pragma unroll
        for (int k = 0; k < 6; k++) a[k] = warpsum(a[k]);

        {   // gates (all lanes redundantly; h1c[j] protected by own-push order)
            float h1old = h1c[j];
            float r_ = sigF(pr + a[0] + a[3] + sbhhL[warp * 3 + 0]);
            float z_ = sigF(pz + a[1] + a[4] + sbhhL[warp * 3 + 1]);
            float n_ = tanF(pn + a[2] + r_ * (a[5] + sbhhL[warp * 3 + 2]));
            float h1n = (1.f - z_) * n_ + z_ * h1old;
            if (lane == 0) g_Lout[t * 256 + j] = h1n;
            if (t < T_STEPS - 1 && lane < 16)
                dsm_store2(nb ? raM1[1] : raM1[0],
                           __float_as_uint(h1n), (uint32_t)(t + 1));
        }
        if (t == T_STEPS - 1) break;

        // ---- phase B ----
        float b_[6];
        {   // local hh dots first (h2c stable until next phase-A poll)
            const float4* xp = (const float4*)h2c;
            float4 xlo = xp[lane * 2], xhi = xp[lane * 2 + 1];
            b_[3] = dot4(wB[3][0], xlo) + dot4(wB[3][1], xhi);
            b_[4] = dot4(wB[4][0], xlo) + dot4(wB[4][1], xhi);
            b_[5] = dot4(wB[5][0], xlo) + dot4(wB[5][1], xhi);
        }
        if (tid < 256)
            h1c[tid] = poll_mb(pl1[nb], (uint32_t)(t + 1));
        __syncthreads();
        {
            const float4* xp = (const float4*)h1c;
            float4 xlo = xp[lane * 2], xhi = xp[lane * 2 + 1];
            b_[0] = dot4(wB[0][0], xlo) + dot4(wB[0][1], xhi);
            b_[1] = dot4(wB[1][0], xlo) + dot4(wB[1][1], xhi);
            b_[2] = dot4(wB[2][0], xlo) + dot4(wB[2][1], xhi);
        }
#pragma unroll
        for (int k = 0; k < 6; k++) b_[k] = warpsum(b_[k]);

        {
            float h2old = h2c[j];
            float r_ = sigF(b_[0] + sbihH[warp * 3 + 0] +
                            b_[3] + sbhhH[warp * 3 + 0]);
            float z_ = sigF(b_[1] + sbihH[warp * 3 + 1] +
                            b_[4] + sbhhH[warp * 3 + 1]);
            float n_ = tanF(b_[2] + sbihH[warp * 3 + 2] +
                            r_ * (b_[5] + sbhhH[warp * 3 + 2]));
            float h2n = (1.f - z_) * n_ + z_ * h2old;
            if (lane < 16)
                dsm_store2(nb ? raM2[1] : raM2[0],
                           __float_as_uint(h2n), (uint32_t)(t + 1));
        }
    }

    // teardown rendezvous for cluster-lifetime safety
    CLUSTER_ARRIVE(); CLUSTER_WAIT();
}

// ---------------- k2 fallback: L2-flag scan (proven) ----------------
extern __shared__ float smw[];
__global__ void __launch_bounds__(256, 1) k2_scan(
    const float* __restrict__ WihL, const float* __restrict__ WhhL,
    const float* __restrict__ bhhLg,
    const float* __restrict__ WihH, const float* __restrict__ WhhH,
    const float* __restrict__ bihHg, const float* __restrict__ bhhHg)
{
    float* wA = smw;
    float* wB = smw + 48 * 256;
    __shared__ float dots[48], preS[24], bA[24], bB1[24], bB2[24];

    int tid = threadIdx.x, warp = tid >> 5, lane = tid & 31, cta = blockIdx.x;
    int j0 = cta * 8;
    {
        int r4 = tid >> 6, c = tid & 63;
        for (int d0 = 0; d0 < 48; d0 += 4) {
            int d = d0 + r4;
            int jj = (d % 24) / 3, r = d % 3, grow = j0 + jj + 256 * r;
            const float4* srcA = (d < 24)
                ? (const float4*)(WihL + grow * 512 + 256)
                : (const float4*)(WhhL + grow * 256);
            ((float4*)(wA + d * 256))[c] = __ldg(srcA + c);
            const float4* srcB = (d < 24)
                ? (const float4*)(WihH + grow * 256)
                : (const float4*)(WhhH + grow * 256);
            ((float4*)(wB + d * 256))[c] = __ldg(srcB + c);
        }
    }
    if (tid < 24) {
        int jj = tid / 3, r = tid % 3, grow = j0 + jj + 256 * r;
        bA[tid] = bhhLg[grow]; bB1[tid] = bihHg[grow]; bB2[tid] = bhhHg[grow];
    }
    __syncthreads();

    for (int t = 0; t < T_STEPS; t++) {
        if (tid < 24)
            preS[tid] = __ldg(&g_pre[t * 768 + j0 + (tid / 3) + 256 * (tid % 3)]);
        const float* h1r = g_h1[t & 1];
        const float* h2r = g_h2[t & 1];
        float* h1w = g_h1[(t & 1) ^ 1];
        float* h2w = g_h2[(t & 1) ^ 1];
        float4 h1a = __ldcg((const float4*)h1r + lane);
        float4 h1b = __ldcg((const float4*)h1r + lane + 32);
        float4 h2a = __ldcg((const float4*)h2r + lane);
        float4 h2b = __ldcg((const float4*)h2r + lane + 32);
        {
            float p[6];
#pragma unroll
            for (int i = 0; i < 6; i++) {
                const float4* w = (const float4*)(wA + (warp + 8 * i) * 256);
                float4 xa = (i < 3) ? h2a : h1a, xb = (i < 3) ? h2b : h1b;
                p[i] = dot4(w[lane], xa) + dot4(w[lane + 32], xb);
            }
#pragma unroll
            for (int i = 0; i < 6; i++) p[i] = warpsum(p[i]);
            if (lane == 0)
#pragma unroll
                for (int i = 0; i < 6; i++) dots[warp + 8 * i] = p[i];
        }
        __syncthreads();
        if (tid < 8) {
            int jj = tid, j = j0 + jj;
            float r_ = sigf(preS[jj*3+0] + dots[jj*3+0] + dots[24+jj*3+0] + bA[jj*3+0]);
            float z_ = sigf(preS[jj*3+1] + dots[jj*3+1] + dots[24+jj*3+1] + bA[jj*3+1]);
            float n_ = tanhf(preS[jj*3+2] + dots[jj*3+2] + r_*(dots[24+jj*3+2] + bA[jj*3+2]));
            float h1n = (1.f - z_) * n_ + z_ * __ldcg(h1r + j);
            h1w[j] = h1n;
            g_Lout[t * 256 + j] = h1n;
        }
        if (t == T_STEPS - 1) break;
        gridbar(2 * t + 1, tid, cta);
        float4 na = __ldcg((const float4*)h1w + lane);
        float4 nb4 = __ldcg((const float4*)h1w + lane + 32);
        {
            float p[6];
#pragma unroll
            for (int i = 0; i < 6; i++) {
                const float4* w = (const float4*)(wB + (warp + 8 * i) * 256);
                float4 xa = (i < 3) ? na : h2a, xb = (i < 3) ? nb4 : h2b;
                p[i] = dot4(w[lane], xa) + dot4(w[lane + 32], xb);
            }
#pragma unroll
            for (int i = 0; i < 6; i++) p[i] = warpsum(p[i]);
            if (lane == 0)
#pragma unroll
                for (int i = 0; i < 6; i++) dots[warp + 8 * i] = p[i];
        }
        __syncthreads();
        if (tid < 8) {
            int jj = tid, j = j0 + jj;
            float r_ = sigf(dots[jj*3+0] + bB1[jj*3+0] + dots[24+jj*3+0] + bB2[jj*3+0]);
            float z_ = sigf(dots[jj*3+1] + bB1[jj*3+1] + dots[24+jj*3+1] + bB2[jj*3+1]);
            float n_ = tanhf(dots[jj*3+2] + bB1[jj*3+2] + r_*(dots[24+jj*3+2] + bB2[jj*3+2]));
            h2w[j] = (1.f - z_) * n_ + z_ * __ldcg(h2r + j);
        }
        gridbar(2 * t + 2, tid, cta);
    }
}

// ---------------- k3: output heads (grid 50x16, 48 rows/block) ----------------
__global__ void __launch_bounds__(256) k3_out(
    const float* __restrict__ W2v, const float* __restrict__ b2v,
    const float* __restrict__ W2m, const float* __restrict__ b2m,
    float* __restrict__ out)
{
    int t = blockIdx.x, s = blockIdx.y;
    int tid = threadIdx.x, warp = tid >> 5, lane = tid & 31;
    __shared__ __align__(16) float fv[128], fm[128];
    if (tid < 128) fv[tid] = eluf(g_Lout[t * 256 + tid]);
    else           fm[tid - 128] = eluf(g_Lout[t * 256 + tid]);
    __syncthreads();

    const float4* fv4 = (const float4*)fv;
#pragma unroll
    for (int b = 0; b < 3; b++) {
        float p[2];
#pragma unroll
        for (int u = 0; u < 2; u++) {
            int i = s * 48 + warp + 8 * (b * 2 + u);
            p[u] = dot4(__ldg((const float4*)(W2v + i * 128) + lane), fv4[lane]);
        }
#pragma unroll
        for (int u = 0; u < 2; u++) {
            p[u] = warpsum(p[u]);
            int i = s * 48 + warp + 8 * (b * 2 + u);
            if (lane == 0) out[t * 768 + i] = sigf(p[u] + b2v[i]);
        }
    }
    if (s == 0 && warp < 2) {
        const float4* fm4 = (const float4*)fm;
        float v = dot4(__ldg((const float4*)(W2m + warp * 128) + lane), fm4[lane]);
        v = warpsum(v);
        if (lane == 0) out[T_STEPS * 768 + t * 2 + warp] = tanhf(v + b2m[warp]);
    }
}

// ---------------- launch ----------------
extern "C" void kernel_launch(void* const* d_in, const int* in_sizes, int n_in,
                              void* d_out, int out_size) {
    const float* v0   = (const float*)d_in[0];
    const float* m0   = (const float*)d_in[1];
    const float* W1v  = (const float*)d_in[2];
    const float* b1v  = (const float*)d_in[3];
    const float* W1m  = (const float*)d_in[4];
    const float* b1m  = (const float*)d_in[5];
    const float* WihL = (const float*)d_in[6];
    const float* WhhL = (const float*)d_in[7];
    const float* bihL = (const float*)d_in[8];
    const float* bhhL = (const float*)d_in[9];
    const float* WihH = (const float*)d_in[10];
    const float* WhhH = (const float*)d_in[11];
    const float* bihH = (const float*)d_in[12];
    const float* bhhH = (const float*)d_in[13];
    const float* W2v  = (const float*)d_in[14];
    const float* b2v  = (const float*)d_in[15];
    const float* W2m  = (const float*)d_in[16];
    const float* b2m  = (const float*)d_in[17];
    float* out = (float*)d_out;

    const int FB_SMEM = 96 * 256 * 4;
    cudaFuncSetAttribute(k2_cluster, cudaFuncAttributeNonPortableClusterSizeAllowed, 1);
    cudaFuncSetAttribute(k2_scan, cudaFuncAttributeMaxDynamicSharedMemorySize, FB_SMEM);

    k1a_feat<<<dim3(T_STEPS, 8), 256>>>(v0, m0, W1v, b1v, W1m, b1m);
    k1b_pre <<<dim3(T_STEPS, 12), 256>>>(WihL, bihL);

    cudaLaunchConfig_t cfg = {};
    cfg.gridDim = dim3(CL, 1, 1);
    cfg.blockDim = dim3(512, 1, 1);
    cfg.dynamicSmemBytes = 0;
    cfg.stream = 0;
    cudaLaunchAttribute attrs[1];
    attrs[0].id = cudaLaunchAttributeClusterDimension;
    attrs[0].val.clusterDim = {CL, 1, 1};
    cfg.attrs = attrs;
    cfg.numAttrs = 1;
    cudaError_t st = cudaLaunchKernelEx(&cfg, k2_cluster,
                                        WihL, WhhL, bhhL, WihH, WhhH, bihH, bhhH);
    if (st != cudaSuccess) {
        (void)cudaGetLastError();  // clear; deterministic proven fallback
        k2_scan<<<NB2, 256, FB_SMEM>>>(WihL, WhhL, bhhL, WihH, WhhH, bihH, bhhH);
    }

    k3_out<<<dim3(T_STEPS, 16), 256>>>(W2v, b2v, W2m, b2m, out);
}